// round 8
// baseline (speedup 1.0000x reference)
#include <cuda_runtime.h>
#include <cuda_bf16.h>
#include <cstdint>

// ForceGrid: NGP deposit of 10M weighted particles into a 256^3 float grid.
// fi5 = RN(RN(RN(x+10) * 12.75f) + 0.5f)  (replicates XLA's reciprocal-mul),
// index = trunc(fi5), in-bounds -> red.add with L2 evict_last pin (R6 win).
// R8: 256-bit loads (ld.global.v8.f32, sm_100+) — 4 LDG.256 per 8 particles
// instead of 8 LDG.128, halving load-issue slots and L1tex load wavefronts.

#define GRID_N 256

__device__ __forceinline__ uint64_t make_evict_last_policy() {
    uint64_t pol;
    asm volatile("createpolicy.fractional.L2::evict_last.b64 %0, 1.0;" : "=l"(pol));
    return pol;
}

// 256-bit streaming load: 8 consecutive f32.
__device__ __forceinline__ void ldg256_cs(const float* p, float* r) {
    asm volatile("ld.global.cs.v8.f32 {%0,%1,%2,%3,%4,%5,%6,%7}, [%8];"
                 : "=f"(r[0]), "=f"(r[1]), "=f"(r[2]), "=f"(r[3]),
                   "=f"(r[4]), "=f"(r[5]), "=f"(r[6]), "=f"(r[7])
                 : "l"(p));
}

__device__ __forceinline__ void deposit_one(float x, float y, float z, float w,
                                            float* __restrict__ grid,
                                            uint64_t pol) {
    const float R = 12.75f;  // RN(1 / RN(20/255)) == 12.75 exactly
    float fx = __fadd_rn(__fmul_rn(__fadd_rn(x, 10.0f), R), 0.5f);
    float fy = __fadd_rn(__fmul_rn(__fadd_rn(y, 10.0f), R), 0.5f);
    float fz = __fadd_rn(__fmul_rn(__fadd_rn(z, 10.0f), R), 0.5f);
    int ix = (int)fx;   // trunc toward zero == astype(int32)
    int iy = (int)fy;
    int iz = (int)fz;
    if (((unsigned)ix < GRID_N) & ((unsigned)iy < GRID_N) & ((unsigned)iz < GRID_N)) {
        int flat = (ix * GRID_N + iy) * GRID_N + iz;
        asm volatile("red.global.L2::cache_hint.add.f32 [%0], %1, %2;"
                     :: "l"(grid + flat), "f"(w), "l"(pol) : "memory");
    }
}

// Zero the grid with evict_last-policy stores: lines enter L2 dirty + pinned.
__global__ void __launch_bounds__(256)
forcegrid_zero_kernel(float4* __restrict__ grid4, int n4) {
    int i = blockIdx.x * blockDim.x + threadIdx.x;
    int stride = gridDim.x * blockDim.x;
    const float z = 0.0f;
    const uint64_t pol = make_evict_last_policy();
    for (; i < n4; i += stride) {
        asm volatile("st.global.L2::cache_hint.v4.f32 [%0], {%1, %2, %3, %4}, %5;"
                     :: "l"(grid4 + i), "f"(z), "f"(z), "f"(z), "f"(z), "l"(pol)
                     : "memory");
    }
}

__global__ void __launch_bounds__(256)
forcegrid_deposit_kernel(const float*  __restrict__ positions,
                         const float*  __restrict__ weights,
                         float* __restrict__ grid,
                         int n_particles) {
    const int noct = n_particles >> 3;               // groups of 8 particles
    const int stride = gridDim.x * blockDim.x;
    const uint64_t pol = make_evict_last_policy();

    for (int t = blockIdx.x * blockDim.x + threadIdx.x; t < noct; t += stride) {
        // 8 particles: 3 x 256-bit position loads (24 f32) + 1 x 256-bit weights.
        float p[24], w[8];
        const float* pbase = positions + 24 * (size_t)t;
        ldg256_cs(pbase,      p);
        ldg256_cs(pbase + 8,  p + 8);
        ldg256_cs(pbase + 16, p + 16);
        ldg256_cs(weights + 8 * (size_t)t, w);

        #pragma unroll
        for (int k = 0; k < 8; k++)
            deposit_one(p[3*k], p[3*k+1], p[3*k+2], w[k], grid, pol);
    }

    // tail (n_particles % 8 != 0) — single thread, scalar path
    if (blockIdx.x == 0 && threadIdx.x == 0) {
        for (int pi = noct * 8; pi < n_particles; pi++) {
            deposit_one(positions[3 * pi + 0], positions[3 * pi + 1],
                        positions[3 * pi + 2], weights[pi], grid, pol);
        }
    }
}

extern "C" void kernel_launch(void* const* d_in, const int* in_sizes, int n_in,
                              void* d_out, int out_size) {
    const float* positions = (const float*)d_in[0];   // [N,3] f32
    const float* weights   = (const float*)d_in[1];   // [N]   f32
    float* grid = (float*)d_out;                      // 256^3 f32

    int n_particles = in_sizes[1];                    // N from weights

    int threads = 256;

    // Zero + L2-pin the grid (out_size is 256^3, divisible by 4).
    int n4 = out_size / 4;
    int zblocks = 148 * 4;
    forcegrid_zero_kernel<<<zblocks, threads, 0, 0>>>((float4*)d_out, n4);

    // Persistent deposit, grid-stride, 8 particles per iteration.
    int blocks = 148 * 8;
    forcegrid_deposit_kernel<<<blocks, threads, 0, 0>>>(
        positions, weights, grid, n_particles);
}

// round 9
// speedup vs baseline: 1.1494x; 1.1494x over previous
#include <cuda_runtime.h>
#include <cuda_bf16.h>
#include <cstdint>

// ForceGrid: NGP deposit of 10M weighted particles into a 256^3 float grid.
// fi5 = RN(RN(RN(x+10) * 12.75f) + 0.5f)  (replicates XLA's reciprocal-mul),
// index = trunc(fi5), in-bounds -> red.add with L2 evict_last pin (R6 win).
// R9: R6 pipeline structure (LDG.128 quads, double-buffered, evict_last pin)
// widened to TWO independent quads per stage (8 particles/iter, MLP_p1=8).

#define GRID_N 256

__device__ __forceinline__ uint64_t make_evict_last_policy() {
    uint64_t pol;
    asm volatile("createpolicy.fractional.L2::evict_last.b64 %0, 1.0;" : "=l"(pol));
    return pol;
}

__device__ __forceinline__ void deposit_one(float x, float y, float z, float w,
                                            float* __restrict__ grid,
                                            uint64_t pol) {
    const float R = 12.75f;  // RN(1 / RN(20/255)) == 12.75 exactly
    float fx = __fadd_rn(__fmul_rn(__fadd_rn(x, 10.0f), R), 0.5f);
    float fy = __fadd_rn(__fmul_rn(__fadd_rn(y, 10.0f), R), 0.5f);
    float fz = __fadd_rn(__fmul_rn(__fadd_rn(z, 10.0f), R), 0.5f);
    int ix = (int)fx;   // trunc toward zero == astype(int32)
    int iy = (int)fy;
    int iz = (int)fz;
    if (((unsigned)ix < GRID_N) & ((unsigned)iy < GRID_N) & ((unsigned)iz < GRID_N)) {
        int flat = (ix * GRID_N + iy) * GRID_N + iz;
        asm volatile("red.global.L2::cache_hint.add.f32 [%0], %1, %2;"
                     :: "l"(grid + flat), "f"(w), "l"(pol) : "memory");
    }
}

__device__ __forceinline__ void deposit_quad(const float4& a, const float4& b,
                                             const float4& c, const float4& w,
                                             float* __restrict__ grid, uint64_t pol) {
    deposit_one(a.x, a.y, a.z, w.x, grid, pol);
    deposit_one(a.w, b.x, b.y, w.y, grid, pol);
    deposit_one(b.z, b.w, c.x, w.z, grid, pol);
    deposit_one(c.y, c.z, c.w, w.w, grid, pol);
}

// Zero the grid with evict_last-policy stores: lines enter L2 dirty + pinned.
__global__ void __launch_bounds__(256)
forcegrid_zero_kernel(float4* __restrict__ grid4, int n4) {
    int i = blockIdx.x * blockDim.x + threadIdx.x;
    int stride = gridDim.x * blockDim.x;
    const float z = 0.0f;
    const uint64_t pol = make_evict_last_policy();
    for (; i < n4; i += stride) {
        asm volatile("st.global.L2::cache_hint.v4.f32 [%0], {%1, %2, %3, %4}, %5;"
                     :: "l"(grid4 + i), "f"(z), "f"(z), "f"(z), "f"(z), "l"(pol)
                     : "memory");
    }
}

__global__ void __launch_bounds__(256)
forcegrid_deposit_kernel(const float4* __restrict__ pos4,
                         const float4* __restrict__ w4,
                         const float*  __restrict__ pos_scalar,
                         const float*  __restrict__ w_scalar,
                         float* __restrict__ grid,
                         int n_particles) {
    const int no = n_particles >> 3;                 // octets (2 quads each)
    const int stride = gridDim.x * blockDim.x;
    int t = blockIdx.x * blockDim.x + threadIdx.x;
    const uint64_t pol = make_evict_last_policy();

    // Software pipeline over octets: buffers for 2 quads, prefetch next octet.
    float4 a0, b0, c0, w0, a1, b1, c1, w1;
    bool have = (t < no);
    if (have) {
        const float4* p = &pos4[6 * t];
        a0 = __ldcs(p + 0); b0 = __ldcs(p + 1); c0 = __ldcs(p + 2);
        a1 = __ldcs(p + 3); b1 = __ldcs(p + 4); c1 = __ldcs(p + 5);
        w0 = __ldcs(&w4[2 * t]); w1 = __ldcs(&w4[2 * t + 1]);
    }
    while (have) {
        const int tn = t + stride;
        const bool haven = (tn < no);
        float4 an0, bn0, cn0, wn0, an1, bn1, cn1, wn1;
        if (haven) {                                  // prefetch next octet
            const float4* p = &pos4[6 * tn];
            an0 = __ldcs(p + 0); bn0 = __ldcs(p + 1); cn0 = __ldcs(p + 2);
            an1 = __ldcs(p + 3); bn1 = __ldcs(p + 4); cn1 = __ldcs(p + 5);
            wn0 = __ldcs(&w4[2 * tn]); wn1 = __ldcs(&w4[2 * tn + 1]);
        }
        deposit_quad(a0, b0, c0, w0, grid, pol);
        deposit_quad(a1, b1, c1, w1, grid, pol);
        a0 = an0; b0 = bn0; c0 = cn0; w0 = wn0;
        a1 = an1; b1 = bn1; c1 = cn1; w1 = wn1;
        t = tn; have = haven;
    }

    // tail (n_particles % 8 != 0) — single thread, scalar path
    if (blockIdx.x == 0 && threadIdx.x == 0) {
        for (int p = no * 8; p < n_particles; p++) {
            deposit_one(pos_scalar[3 * p + 0], pos_scalar[3 * p + 1],
                        pos_scalar[3 * p + 2], w_scalar[p], grid, pol);
        }
    }
}

extern "C" void kernel_launch(void* const* d_in, const int* in_sizes, int n_in,
                              void* d_out, int out_size) {
    const float* positions = (const float*)d_in[0];   // [N,3] f32
    const float* weights   = (const float*)d_in[1];   // [N]   f32
    float* grid = (float*)d_out;                      // 256^3 f32

    int n_particles = in_sizes[1];                    // N from weights

    int threads = 256;

    // Zero + L2-pin the grid (out_size is 256^3, divisible by 4).
    int n4 = out_size / 4;
    int zblocks = 148 * 4;
    forcegrid_zero_kernel<<<zblocks, threads, 0, 0>>>((float4*)d_out, n4);

    // Persistent deposit with grid-stride double-buffer, 8 particles/iter.
    int blocks = 148 * 8;
    forcegrid_deposit_kernel<<<blocks, threads, 0, 0>>>(
        (const float4*)positions, (const float4*)weights,
        positions, weights, grid, n_particles);
}

// round 10
// speedup vs baseline: 1.1660x; 1.0145x over previous
#include <cuda_runtime.h>
#include <cuda_bf16.h>
#include <cstdint>

// ForceGrid: NGP deposit of 10M weighted particles into a 256^3 float grid.
// fi5 = RN(RN(RN(x+10) * 12.75f) + 0.5f)  (replicates XLA's reciprocal-mul),
// index = trunc(fi5), in-bounds -> red.add with L2 evict_last pin (R6 win).
// R10: exact R6 structure, but the bounds check is a PREDICATE on the red
// instruction (setp + @p red) instead of a C if around volatile asm —
// eliminates the BSSY/BRA/BSYNC divergence envelope per deposit.

#define GRID_N 256

__device__ __forceinline__ uint64_t make_evict_last_policy() {
    uint64_t pol;
    asm volatile("createpolicy.fractional.L2::evict_last.b64 %0, 1.0;" : "=l"(pol));
    return pol;
}

__device__ __forceinline__ void deposit_one(float x, float y, float z, float w,
                                            float* __restrict__ grid,
                                            uint64_t pol) {
    const float R = 12.75f;  // RN(1 / RN(20/255)) == 12.75 exactly
    float fx = __fadd_rn(__fmul_rn(__fadd_rn(x, 10.0f), R), 0.5f);
    float fy = __fadd_rn(__fmul_rn(__fadd_rn(y, 10.0f), R), 0.5f);
    float fz = __fadd_rn(__fmul_rn(__fadd_rn(z, 10.0f), R), 0.5f);
    int ix = (int)fx;   // trunc toward zero == astype(int32)
    int iy = (int)fy;
    int iz = (int)fz;
    unsigned ok = ((unsigned)ix < GRID_N) & ((unsigned)iy < GRID_N) &
                  ((unsigned)iz < GRID_N);
    int flat = (ix * GRID_N + iy) * GRID_N + iz;   // garbage when !ok; never used
    // Branch-free predicated reduction with L2 evict_last cache hint.
    asm volatile("{\n\t"
                 ".reg .pred p;\n\t"
                 "setp.ne.u32 p, %3, 0;\n\t"
                 "@p red.global.L2::cache_hint.add.f32 [%0], %1, %2;\n\t"
                 "}"
                 :: "l"(grid + flat), "f"(w), "l"(pol), "r"(ok) : "memory");
}

// Zero the grid with evict_last-policy stores: lines enter L2 dirty + pinned.
__global__ void __launch_bounds__(256)
forcegrid_zero_kernel(float4* __restrict__ grid4, int n4) {
    int i = blockIdx.x * blockDim.x + threadIdx.x;
    int stride = gridDim.x * blockDim.x;
    const float z = 0.0f;
    const uint64_t pol = make_evict_last_policy();
    for (; i < n4; i += stride) {
        asm volatile("st.global.L2::cache_hint.v4.f32 [%0], {%1, %2, %3, %4}, %5;"
                     :: "l"(grid4 + i), "f"(z), "f"(z), "f"(z), "f"(z), "l"(pol)
                     : "memory");
    }
}

__global__ void __launch_bounds__(256)
forcegrid_deposit_kernel(const float4* __restrict__ pos4,
                         const float4* __restrict__ w4,
                         const float*  __restrict__ pos_scalar,
                         const float*  __restrict__ w_scalar,
                         float* __restrict__ grid,
                         int n_particles) {
    const int nq = n_particles >> 2;                 // full quads
    const int stride = gridDim.x * blockDim.x;
    int q = blockIdx.x * blockDim.x + threadIdx.x;
    const uint64_t pol = make_evict_last_policy();

    // Software pipeline: cur regs hold quad q, next loads issue before deposits.
    float4 a, b, c, w;
    bool have = (q < nq);
    if (have) {
        a = __ldcs(&pos4[3 * q + 0]);
        b = __ldcs(&pos4[3 * q + 1]);
        c = __ldcs(&pos4[3 * q + 2]);
        w = __ldcs(&w4[q]);
    }
    while (have) {
        const int qn = q + stride;
        const bool haven = (qn < nq);
        float4 an, bn, cn, wn;
        if (haven) {                                  // prefetch next quad
            an = __ldcs(&pos4[3 * qn + 0]);
            bn = __ldcs(&pos4[3 * qn + 1]);
            cn = __ldcs(&pos4[3 * qn + 2]);
            wn = __ldcs(&w4[qn]);
        }
        deposit_one(a.x, a.y, a.z, w.x, grid, pol);
        deposit_one(a.w, b.x, b.y, w.y, grid, pol);
        deposit_one(b.z, b.w, c.x, w.z, grid, pol);
        deposit_one(c.y, c.z, c.w, w.w, grid, pol);
        a = an; b = bn; c = cn; w = wn;               // rotate buffers
        q = qn; have = haven;
    }

    // tail (n_particles % 4 != 0) — single thread, scalar path
    if (blockIdx.x == 0 && threadIdx.x == 0) {
        for (int p = nq * 4; p < n_particles; p++) {
            deposit_one(pos_scalar[3 * p + 0], pos_scalar[3 * p + 1],
                        pos_scalar[3 * p + 2], w_scalar[p], grid, pol);
        }
    }
}

extern "C" void kernel_launch(void* const* d_in, const int* in_sizes, int n_in,
                              void* d_out, int out_size) {
    const float* positions = (const float*)d_in[0];   // [N,3] f32
    const float* weights   = (const float*)d_in[1];   // [N]   f32
    float* grid = (float*)d_out;                      // 256^3 f32

    int n_particles = in_sizes[1];                    // N from weights

    int threads = 256;

    // Zero + L2-pin the grid (out_size is 256^3, divisible by 4).
    int n4 = out_size / 4;
    int zblocks = 148 * 4;
    forcegrid_zero_kernel<<<zblocks, threads, 0, 0>>>((float4*)d_out, n4);

    // Persistent deposit with grid-stride double-buffer (exact R6 config).
    int blocks = 148 * 8;
    forcegrid_deposit_kernel<<<blocks, threads, 0, 0>>>(
        (const float4*)positions, (const float4*)weights,
        positions, weights, grid, n_particles);
}

// round 11
// speedup vs baseline: 1.2067x; 1.0348x over previous
#include <cuda_runtime.h>
#include <cuda_bf16.h>
#include <cstdint>

// ForceGrid: NGP deposit of 10M weighted particles into a 256^3 float grid.
// fi5 = RN(RN(RN(x+10) * 12.75f) + 0.5f)  (replicates XLA's reciprocal-mul,
// three separately-rounded ops), index = trunc(fi5), in-bounds -> red.add.
// R11: deposit kernel == R6 best (66.0us): double-buffered LDG.128 quads +
// L2 evict_last pin on the reductions. Zero kernel upgraded to 256-bit
// evict_last stores to shorten the serial zero phase.

#define GRID_N 256

__device__ __forceinline__ uint64_t make_evict_last_policy() {
    uint64_t pol;
    asm volatile("createpolicy.fractional.L2::evict_last.b64 %0, 1.0;" : "=l"(pol));
    return pol;
}

__device__ __forceinline__ void deposit_one(float x, float y, float z, float w,
                                            float* __restrict__ grid,
                                            uint64_t pol) {
    const float R = 12.75f;  // RN(1 / RN(20/255)) == 12.75 exactly
    float fx = __fadd_rn(__fmul_rn(__fadd_rn(x, 10.0f), R), 0.5f);
    float fy = __fadd_rn(__fmul_rn(__fadd_rn(y, 10.0f), R), 0.5f);
    float fz = __fadd_rn(__fmul_rn(__fadd_rn(z, 10.0f), R), 0.5f);
    int ix = (int)fx;   // trunc toward zero == astype(int32)
    int iy = (int)fy;
    int iz = (int)fz;
    if (((unsigned)ix < GRID_N) & ((unsigned)iy < GRID_N) & ((unsigned)iz < GRID_N)) {
        int flat = (ix * GRID_N + iy) * GRID_N + iz;
        // Reduction with L2 evict_last cache hint: keeps grid lines resident.
        asm volatile("red.global.L2::cache_hint.add.f32 [%0], %1, %2;"
                     :: "l"(grid + flat), "f"(w), "l"(pol) : "memory");
    }
}

// Zero the grid with 256-bit evict_last-policy stores: lines enter L2
// dirty + pinned, half the store instructions of the v4 version.
__global__ void __launch_bounds__(256)
forcegrid_zero_kernel(float* __restrict__ grid, int n8) {
    int i = blockIdx.x * blockDim.x + threadIdx.x;
    int stride = gridDim.x * blockDim.x;
    const float z = 0.0f;
    const uint64_t pol = make_evict_last_policy();
    for (; i < n8; i += stride) {
        asm volatile(
            "st.global.L2::cache_hint.v8.f32 [%0], {%1,%2,%3,%4,%5,%6,%7,%8}, %9;"
            :: "l"(grid + 8 * (size_t)i),
               "f"(z), "f"(z), "f"(z), "f"(z), "f"(z), "f"(z), "f"(z), "f"(z),
               "l"(pol)
            : "memory");
    }
}

__global__ void __launch_bounds__(256)
forcegrid_deposit_kernel(const float4* __restrict__ pos4,
                         const float4* __restrict__ w4,
                         const float*  __restrict__ pos_scalar,
                         const float*  __restrict__ w_scalar,
                         float* __restrict__ grid,
                         int n_particles) {
    const int nq = n_particles >> 2;                 // full quads
    const int stride = gridDim.x * blockDim.x;
    int q = blockIdx.x * blockDim.x + threadIdx.x;
    const uint64_t pol = make_evict_last_policy();

    // Software pipeline: cur regs hold quad q, next loads issue before deposits.
    float4 a, b, c, w;
    bool have = (q < nq);
    if (have) {
        a = __ldcs(&pos4[3 * q + 0]);
        b = __ldcs(&pos4[3 * q + 1]);
        c = __ldcs(&pos4[3 * q + 2]);
        w = __ldcs(&w4[q]);
    }
    while (have) {
        const int qn = q + stride;
        const bool haven = (qn < nq);
        float4 an, bn, cn, wn;
        if (haven) {                                  // prefetch next quad
            an = __ldcs(&pos4[3 * qn + 0]);
            bn = __ldcs(&pos4[3 * qn + 1]);
            cn = __ldcs(&pos4[3 * qn + 2]);
            wn = __ldcs(&w4[qn]);
        }
        deposit_one(a.x, a.y, a.z, w.x, grid, pol);
        deposit_one(a.w, b.x, b.y, w.y, grid, pol);
        deposit_one(b.z, b.w, c.x, w.z, grid, pol);
        deposit_one(c.y, c.z, c.w, w.w, grid, pol);
        a = an; b = bn; c = cn; w = wn;               // rotate buffers
        q = qn; have = haven;
    }

    // tail (n_particles % 4 != 0) — single thread, scalar path
    if (blockIdx.x == 0 && threadIdx.x == 0) {
        for (int p = nq * 4; p < n_particles; p++) {
            deposit_one(pos_scalar[3 * p + 0], pos_scalar[3 * p + 1],
                        pos_scalar[3 * p + 2], w_scalar[p], grid, pol);
        }
    }
}

extern "C" void kernel_launch(void* const* d_in, const int* in_sizes, int n_in,
                              void* d_out, int out_size) {
    const float* positions = (const float*)d_in[0];   // [N,3] f32
    const float* weights   = (const float*)d_in[1];   // [N]   f32
    float* grid = (float*)d_out;                      // 256^3 f32

    int n_particles = in_sizes[1];                    // N from weights

    int threads = 256;

    // Zero + L2-pin the grid (out_size = 256^3, divisible by 8).
    int n8 = out_size / 8;
    int zblocks = 148 * 4;
    forcegrid_zero_kernel<<<zblocks, threads, 0, 0>>>(grid, n8);

    // Persistent deposit with grid-stride double-buffer (exact R6 config).
    int blocks = 148 * 8;
    forcegrid_deposit_kernel<<<blocks, threads, 0, 0>>>(
        (const float4*)positions, (const float4*)weights,
        positions, weights, grid, n_particles);
}